// round 3
// baseline (speedup 1.0000x reference)
#include <cuda_runtime.h>
#include <math.h>

#define TILE 32
#define STR  36
#define NT   480
#define SMEM_FLOATS ((795 + 405) * STR)

__device__ __forceinline__ float gelu_f(float v) {
    return 0.5f * v * (1.0f + erff(v * 0.70710678118654752f));
}

// acc[0..7] += In[(base + j*step)][s..s+7] * wr[j]  for j in [0,J)
template<int J>
__device__ __forceinline__ void mm_rows(const float* __restrict__ wr,
                                        const float* __restrict__ In,
                                        int base, int step, int s, float* acc) {
    #pragma unroll
    for (int j = 0; j < J; j++) {
        const float4* p = (const float4*)(In + (base + j * step) * STR + s);
        float4 a = p[0], b = p[1];
        float wv = wr[j];
        acc[0] = fmaf(wv, a.x, acc[0]); acc[1] = fmaf(wv, a.y, acc[1]);
        acc[2] = fmaf(wv, a.z, acc[2]); acc[3] = fmaf(wv, a.w, acc[3]);
        acc[4] = fmaf(wv, b.x, acc[4]); acc[5] = fmaf(wv, b.y, acc[5]);
        acc[6] = fmaf(wv, b.z, acc[6]); acc[7] = fmaf(wv, b.w, acc[7]);
    }
}

// Block-diagonal mm1: Out[o][s] = sum_p In[(o/Q)*P + p][s] * W[o*P + p]
template<int O, int Q, int P>
__device__ __forceinline__ void phase_mm1(int tid, const float* __restrict__ W,
                                          const float* __restrict__ In,
                                          float* __restrict__ Out) {
    if (tid < O) {
        int k = tid / Q;
        float wr[P];
        #pragma unroll
        for (int j = 0; j < P; j++) wr[j] = W[tid * P + j];
        #pragma unroll 1
        for (int s = 0; s < TILE; s += 8) {
            float acc[8] = {0.f,0.f,0.f,0.f,0.f,0.f,0.f,0.f};
            mm_rows<P>(wr, In, k * P, 1, s, acc);
            float4* op = (float4*)(Out + tid * STR + s);
            op[0] = make_float4(acc[0], acc[1], acc[2], acc[3]);
            op[1] = make_float4(acc[4], acc[5], acc[6], acc[7]);
        }
    }
}

// Permute + block-diagonal mm2 (+bias, optional gelu), store at f = s2*15+l if f < nOut.
// In row for (l, r) is r*15 + l  (out1 flat viewed as (r, l) then transposed).
template<int O, int S2, int R, bool GELU>
__device__ __forceinline__ void phase_mm2(int tid, const float* __restrict__ W,
                                          const float* __restrict__ bias,
                                          const float* __restrict__ In,
                                          float* __restrict__ Out, int nOut) {
    if (tid < O) {
        int l = tid / S2, s2 = tid - l * S2;
        int f = s2 * 15 + l;
        float wr[R];
        #pragma unroll
        for (int j = 0; j < R; j++) wr[j] = W[tid * R + j];
        float bb = (f < nOut) ? bias[f] : 0.f;
        #pragma unroll 1
        for (int s = 0; s < TILE; s += 8) {
            float acc[8] = {0.f,0.f,0.f,0.f,0.f,0.f,0.f,0.f};
            mm_rows<R>(wr, In, l, 15, s, acc);
            if (f < nOut) {
                #pragma unroll
                for (int u = 0; u < 8; u++) {
                    float v = acc[u] + bb;
                    Out[f * STR + s + u] = GELU ? gelu_f(v) : v;
                }
            }
        }
    }
}

__device__ __forceinline__ void pad_rows(int tid, float* __restrict__ Out, int lo, int hi) {
    int n = (hi - lo) * TILE;
    for (int i = tid; i < n; i += NT)
        Out[(lo + i / TILE) * STR + (i % TILE)] = 0.f;
}

__global__ void __launch_bounds__(NT, 1) monarch_kernel(
    const float* __restrict__ x, int B,
    const float* __restrict__ w11, const float* __restrict__ w12, const float* __restrict__ b1,
    const float* __restrict__ w21, const float* __restrict__ w22, const float* __restrict__ b2,
    const float* __restrict__ w31, const float* __restrict__ w32, const float* __restrict__ b3,
    const float* __restrict__ w41, const float* __restrict__ w42, const float* __restrict__ b4,
    float* __restrict__ out)
{
    extern __shared__ float sm[];
    float* X = sm;                 // up to 795 rows x STR
    float* Y = sm + 795 * STR;     // up to 405 rows x STR
    const int tid = threadIdx.x;
    const int s0 = blockIdx.x * TILE;

    // Load input tile (32 x 784) transposed into X, pad rows 784..794 with zeros.
    {
        const float* xb = x + (size_t)s0 * 784;
        const int lim = TILE * 784;
        for (int idx = tid; idx < lim; idx += NT) {
            int s = idx / 784, i = idx - s * 784;
            float v = (s0 + s < B) ? __ldcg(xb + idx) : 0.f;
            X[i * STR + s] = v;
        }
        pad_rows(tid, X, 784, 795);
    }
    __syncthreads();

    // Layer 1: (15,27,53) / (15,27,27), out 392
    phase_mm1<405, 27, 53>(tid, w11, X, Y);
    __syncthreads();
    phase_mm2<405, 27, 27, true>(tid, w12, b1, Y, X, 392);
    pad_rows(tid, X, 392, 405);
    __syncthreads();

    // Layer 2: (15,9,27) / (15,9,9), out 128
    phase_mm1<135, 9, 27>(tid, w21, X, Y);
    __syncthreads();
    phase_mm2<135, 9, 9, true>(tid, w22, b2, Y, X, 128);
    pad_rows(tid, X, 128, 135);
    __syncthreads();

    // Layer 3: (15,5,9) / (15,5,5), out 64
    phase_mm1<75, 5, 9>(tid, w31, X, Y);
    __syncthreads();
    phase_mm2<75, 5, 5, true>(tid, w32, b3, Y, X, 64);
    pad_rows(tid, X, 64, 75);
    __syncthreads();

    // Layer 4 mm1: (15,1,5) -> Y[0..14]
    phase_mm1<15, 1, 5>(tid, w41, X, Y);
    __syncthreads();

    // Layer 4 mm2 (l,s=1,r=1): logits[l] = Y[l]*w42[l] + b4[l], l<10; then log-softmax.
    if (tid < TILE && s0 + tid < B) {
        const int s = tid;
        float logit[10];
        float m = -1e30f;
        #pragma unroll
        for (int l = 0; l < 10; l++) {
            float v = Y[l * STR + s] * w42[l] + b4[l];
            logit[l] = v;
            m = fmaxf(m, v);
        }
        float sum = 0.f;
        #pragma unroll
        for (int l = 0; l < 10; l++) sum += expf(logit[l] - m);
        float lse = m + logf(sum);
        float* op = out + (size_t)(s0 + s) * 10;
        #pragma unroll
        for (int l = 0; l < 10; l++) op[l] = logit[l] - lse;
    }
}

extern "C" void kernel_launch(void* const* d_in, const int* in_sizes, int n_in,
                              void* d_out, int out_size) {
    const float* x   = (const float*)d_in[0];
    const float* w11 = (const float*)d_in[1];
    const float* w12 = (const float*)d_in[2];
    const float* b1  = (const float*)d_in[3];
    const float* w21 = (const float*)d_in[4];
    const float* w22 = (const float*)d_in[5];
    const float* b2  = (const float*)d_in[6];
    const float* w31 = (const float*)d_in[7];
    const float* w32 = (const float*)d_in[8];
    const float* b3  = (const float*)d_in[9];
    const float* w41 = (const float*)d_in[10];
    const float* w42 = (const float*)d_in[11];
    const float* b4  = (const float*)d_in[12];
    float* out = (float*)d_out;

    int B = in_sizes[0] / 784;
    int grid = (B + TILE - 1) / TILE;
    size_t smem = SMEM_FLOATS * sizeof(float);
    cudaFuncSetAttribute(monarch_kernel,
                         cudaFuncAttributeMaxDynamicSharedMemorySize, (int)smem);
    monarch_kernel<<<grid, NT, smem>>>(x, B, w11, w12, b1, w21, w22, b2,
                                       w31, w32, b3, w41, w42, b4, out);
}

// round 5
// speedup vs baseline: 1.3532x; 1.3532x over previous
#include <cuda_runtime.h>
#include <math.h>

#define TILE 16
#define STR  20
#define NT   480
#define SMEM_FLOATS ((795 + 405) * STR)   // 24000 floats = 96000 B

// Transposed weights: Wt[j*O + o]  (coalesced across output index o)
__device__ float g_wt[38385];
#define OFF11 0      // O=405 J=53
#define OFF12 21465  // O=405 J=27
#define OFF21 32400  // O=135 J=27
#define OFF22 36045  // O=135 J=9
#define OFF31 37260  // O=75  J=9
#define OFF32 37935  // O=75  J=5
#define OFF41 38310  // O=15  J=5
#define WT_TOTAL 38385

__global__ void tw_kernel(const float* __restrict__ w11, const float* __restrict__ w12,
                          const float* __restrict__ w21, const float* __restrict__ w22,
                          const float* __restrict__ w31, const float* __restrict__ w32,
                          const float* __restrict__ w41) {
    int i = blockIdx.x * blockDim.x + threadIdx.x;
    if (i >= WT_TOTAL) return;
    const float* src; int O, J, off;
    if      (i < OFF12) { src = w11; O = 405; J = 53; off = OFF11; }
    else if (i < OFF21) { src = w12; O = 405; J = 27; off = OFF12; }
    else if (i < OFF22) { src = w21; O = 135; J = 27; off = OFF21; }
    else if (i < OFF31) { src = w22; O = 135; J = 9;  off = OFF22; }
    else if (i < OFF32) { src = w31; O = 75;  J = 9;  off = OFF31; }
    else if (i < OFF41) { src = w32; O = 75;  J = 5;  off = OFF32; }
    else                { src = w41; O = 15;  J = 5;  off = OFF41; }
    int li = i - off;
    g_wt[i] = src[(li % O) * J + (li / O)];
}

__device__ __forceinline__ float gelu_f(float v) {
    return 0.5f * v * (1.0f + erff(v * 0.70710678118654752f));
}

// Block-diagonal mm1: Out[o][s] = sum_p In[(o/Q)*P + p][s] * W[o][p]
template<int O, int Q, int P>
__device__ __forceinline__ void phase_mm1(int tid, const float* __restrict__ Wt,
                                          const float* __restrict__ In,
                                          float* __restrict__ Out) {
    if (tid < O) {
        const float* inb = In + (tid / Q) * P * STR;
        float acc[TILE];
        #pragma unroll
        for (int u = 0; u < TILE; u++) acc[u] = 0.f;
        #pragma unroll 8
        for (int j = 0; j < P; j++) {
            float wv = Wt[j * O + tid];
            const float4* p = (const float4*)(inb + j * STR);
            #pragma unroll
            for (int c = 0; c < 4; c++) {
                float4 a = p[c];
                acc[c*4+0] = fmaf(wv, a.x, acc[c*4+0]);
                acc[c*4+1] = fmaf(wv, a.y, acc[c*4+1]);
                acc[c*4+2] = fmaf(wv, a.z, acc[c*4+2]);
                acc[c*4+3] = fmaf(wv, a.w, acc[c*4+3]);
            }
        }
        float4* op = (float4*)(Out + tid * STR);
        #pragma unroll
        for (int c = 0; c < 4; c++)
            op[c] = make_float4(acc[c*4], acc[c*4+1], acc[c*4+2], acc[c*4+3]);
    }
}

// Permute + block-diagonal mm2 (+bias, optional gelu), store at f = s2*15+l if f < nOut.
template<int O, int S2, int R, bool GELU>
__device__ __forceinline__ void phase_mm2(int tid, const float* __restrict__ Wt,
                                          const float* __restrict__ bias,
                                          const float* __restrict__ In,
                                          float* __restrict__ Out, int nOut) {
    if (tid < O) {
        int l = tid / S2, s2 = tid - l * S2;
        int f = s2 * 15 + l;
        float acc[TILE];
        #pragma unroll
        for (int u = 0; u < TILE; u++) acc[u] = 0.f;
        #pragma unroll 8
        for (int j = 0; j < R; j++) {
            float wv = Wt[j * O + tid];
            const float4* p = (const float4*)(In + (j * 15 + l) * STR);
            #pragma unroll
            for (int c = 0; c < 4; c++) {
                float4 a = p[c];
                acc[c*4+0] = fmaf(wv, a.x, acc[c*4+0]);
                acc[c*4+1] = fmaf(wv, a.y, acc[c*4+1]);
                acc[c*4+2] = fmaf(wv, a.z, acc[c*4+2]);
                acc[c*4+3] = fmaf(wv, a.w, acc[c*4+3]);
            }
        }
        if (f < nOut) {
            float bb = bias[f];
            float4* op = (float4*)(Out + f * STR);
            #pragma unroll
            for (int c = 0; c < 4; c++) {
                float v0 = acc[c*4+0] + bb, v1 = acc[c*4+1] + bb;
                float v2 = acc[c*4+2] + bb, v3 = acc[c*4+3] + bb;
                if (GELU) { v0 = gelu_f(v0); v1 = gelu_f(v1); v2 = gelu_f(v2); v3 = gelu_f(v3); }
                op[c] = make_float4(v0, v1, v2, v3);
            }
        }
    }
}

__device__ __forceinline__ void pad_rows(int tid, float* __restrict__ Out, int lo, int hi) {
    int n = (hi - lo) * TILE;
    for (int i = tid; i < n; i += NT)
        Out[(lo + i / TILE) * STR + (i % TILE)] = 0.f;
}

__global__ void __launch_bounds__(NT, 2) monarch_kernel(
    const float* __restrict__ x, int B,
    const float* __restrict__ b1, const float* __restrict__ b2,
    const float* __restrict__ b3, const float* __restrict__ w42,
    const float* __restrict__ b4,
    float* __restrict__ out)
{
    extern __shared__ float sm[];
    float* X = sm;                 // up to 795 rows x STR
    float* Y = sm + 795 * STR;     // up to 405 rows x STR
    const int tid = threadIdx.x;
    const int s0 = blockIdx.x * TILE;

    // Load input tile (16 x 784) transposed into X, pad rows 784..794 with zeros.
    {
        const float* xb = x + (size_t)s0 * 784;
        const int lim4 = TILE * 196;   // float4 count
        for (int idx = tid; idx < lim4; idx += NT) {
            int s = idx / 196, i4 = idx - s * 196;
            float4 v = make_float4(0.f, 0.f, 0.f, 0.f);
            if (s0 + s < B) v = __ldcg((const float4*)xb + idx);
            int i = i4 * 4;
            X[(i + 0) * STR + s] = v.x;
            X[(i + 1) * STR + s] = v.y;
            X[(i + 2) * STR + s] = v.z;
            X[(i + 3) * STR + s] = v.w;
        }
        pad_rows(tid, X, 784, 795);
    }
    __syncthreads();

    // Layer 1: (15,27,53) / (15,27,27), out 392
    phase_mm1<405, 27, 53>(tid, g_wt + OFF11, X, Y);
    __syncthreads();
    phase_mm2<405, 27, 27, true>(tid, g_wt + OFF12, b1, Y, X, 392);
    pad_rows(tid, X, 392, 405);
    __syncthreads();

    // Layer 2: (15,9,27) / (15,9,9), out 128
    phase_mm1<135, 9, 27>(tid, g_wt + OFF21, X, Y);
    __syncthreads();
    phase_mm2<135, 9, 9, true>(tid, g_wt + OFF22, b2, Y, X, 128);
    pad_rows(tid, X, 128, 135);
    __syncthreads();

    // Layer 3: (15,5,9) / (15,5,5), out 64
    phase_mm1<75, 5, 9>(tid, g_wt + OFF31, X, Y);
    __syncthreads();
    phase_mm2<75, 5, 5, true>(tid, g_wt + OFF32, b3, Y, X, 64);
    pad_rows(tid, X, 64, 75);
    __syncthreads();

    // Layer 4 mm1: (15,1,5) -> Y[0..14]
    phase_mm1<15, 1, 5>(tid, g_wt + OFF41, X, Y);
    __syncthreads();

    // Layer 4 mm2 (s=1,r=1): logits[l] = Y[l]*w42[l] + b4[l]; then log-softmax.
    if (tid < TILE && s0 + tid < B) {
        const int s = tid;
        float logit[10];
        float m = -1e30f;
        #pragma unroll
        for (int l = 0; l < 10; l++) {
            float v = Y[l * STR + s] * w42[l] + b4[l];
            logit[l] = v;
            m = fmaxf(m, v);
        }
        float sum = 0.f;
        #pragma unroll
        for (int l = 0; l < 10; l++) sum += expf(logit[l] - m);
        float lse = m + logf(sum);
        float* op = out + (size_t)(s0 + s) * 10;
        #pragma unroll
        for (int l = 0; l < 10; l++) op[l] = logit[l] - lse;
    }
}

extern "C" void kernel_launch(void* const* d_in, const int* in_sizes, int n_in,
                              void* d_out, int out_size) {
    const float* x   = (const float*)d_in[0];
    const float* w11 = (const float*)d_in[1];
    const float* w12 = (const float*)d_in[2];
    const float* b1  = (const float*)d_in[3];
    const float* w21 = (const float*)d_in[4];
    const float* w22 = (const float*)d_in[5];
    const float* b2  = (const float*)d_in[6];
    const float* w31 = (const float*)d_in[7];
    const float* w32 = (const float*)d_in[8];
    const float* b3  = (const float*)d_in[9];
    const float* w41 = (const float*)d_in[10];
    const float* w42 = (const float*)d_in[11];
    const float* b4  = (const float*)d_in[12];
    float* out = (float*)d_out;

    int B = in_sizes[0] / 784;

    tw_kernel<<<(WT_TOTAL + 255) / 256, 256>>>(w11, w12, w21, w22, w31, w32, w41);

    int grid = (B + TILE - 1) / TILE;
    size_t smem = SMEM_FLOATS * sizeof(float);
    cudaFuncSetAttribute(monarch_kernel,
                         cudaFuncAttributeMaxDynamicSharedMemorySize, (int)smem);
    monarch_kernel<<<grid, NT, smem>>>(x, B, b1, b2, b3, w42, b4, out);
}

// round 6
// speedup vs baseline: 1.5047x; 1.1119x over previous
#include <cuda_runtime.h>
#include <math.h>

#define TILE 32
#define STR  36
#define NT   480
#define SMEM_FLOATS ((795 + 405) * STR)   // 43200 floats = 172800 B

typedef unsigned long long u64;

// ---------------- transposed / padded weight scratch ----------------
// A: [j<53][k<15][q<32(pad of 27)]        -> 53*480
// B: [j<27][l<15][s2<32(pad of 27)]       -> 27*480
// C: [j<27][k<15][q<12(pad of 9)]         -> 27*180
// D: [j<9 ][l<15][s2<12(pad of 9)]        -> 9*180
// E: [j<9 ][k<15][q<8 (pad of 5)]         -> 9*120
// G: [j<5 ][l<15][s2<8 (pad of 5)]        -> 5*120
// F: [j<5 ][k<15]                         -> 75
__device__ float g_wt[46635];
#define OA 0
#define OB 25440
#define OC 38400
#define OD 43260
#define OE 44880
#define OG 45960
#define OF 46560
#define WT_TOTAL 46635

__global__ void tw_kernel(const float* __restrict__ w11, const float* __restrict__ w12,
                          const float* __restrict__ w21, const float* __restrict__ w22,
                          const float* __restrict__ w31, const float* __restrict__ w32,
                          const float* __restrict__ w41) {
    int i = blockIdx.x * blockDim.x + threadIdx.x;
    if (i >= WT_TOTAL) return;
    float v;
    if (i < OB) {
        int j = i / 480, r = i % 480, k = r / 32, q = r % 32;
        v = (q < 27) ? w11[(k * 27 + q) * 53 + j] : 0.f;
    } else if (i < OC) {
        int t = i - OB, j = t / 480, r = t % 480, l = r / 32, q = r % 32;
        v = (q < 27) ? w12[(l * 27 + q) * 27 + j] : 0.f;
    } else if (i < OD) {
        int t = i - OC, j = t / 180, r = t % 180, k = r / 12, q = r % 12;
        v = (q < 9) ? w21[(k * 9 + q) * 27 + j] : 0.f;
    } else if (i < OE) {
        int t = i - OD, j = t / 180, r = t % 180, l = r / 12, q = r % 12;
        v = (q < 9) ? w22[(l * 9 + q) * 9 + j] : 0.f;
    } else if (i < OG) {
        int t = i - OE, j = t / 120, r = t % 120, k = r / 8, q = r % 8;
        v = (q < 5) ? w31[(k * 5 + q) * 9 + j] : 0.f;
    } else if (i < OF) {
        int t = i - OG, j = t / 120, r = t % 120, l = r / 8, q = r % 8;
        v = (q < 5) ? w32[(l * 5 + q) * 5 + j] : 0.f;
    } else {
        int t = i - OF, j = t / 15, k = t % 15;
        v = w41[k * 5 + j];
    }
    g_wt[i] = v;
}

// ---------------- packed f32x2 helpers ----------------
__device__ __forceinline__ u64 dup2(float w) {
    u64 r; asm("mov.b64 %0, {%1, %1};" : "=l"(r) : "f"(w)); return r;
}
__device__ __forceinline__ void fma2(u64& d, u64 a, u64 b) {
    asm("fma.rn.f32x2 %0, %1, %2, %0;" : "+l"(d) : "l"(a), "l"(b));
}
__device__ __forceinline__ float2 unp(u64 a) {
    float2 f; asm("mov.b64 {%0, %1}, %2;" : "=f"(f.x), "=f"(f.y) : "l"(a)); return f;
}
__device__ __forceinline__ float gelu_f(float v) {
    return 0.5f * v * (1.0f + erff(v * 0.70710678118654752f));
}

// ---------------- big phases (layer 1): 480 threads, 8 outs x 4 samples ----------------
template<int P>
__device__ __forceinline__ void big_accum(const float* __restrict__ wb,
                                          const float* __restrict__ inb, int jstep,
                                          u64* acc) {
    #pragma unroll
    for (int u = 0; u < 16; u++) acc[u] = 0ull;
    #pragma unroll 4
    for (int j = 0; j < P; j++) {
        float4 w0 = __ldg((const float4*)(wb + j * 480));
        float4 w1 = __ldg((const float4*)(wb + j * 480 + 4));
        const float* ip = inb + j * jstep;
        u64 i01 = *(const u64*)(ip);
        u64 i23 = *(const u64*)(ip + 2);
        fma2(acc[0],  i01, dup2(w0.x)); fma2(acc[1],  i23, dup2(w0.x));
        fma2(acc[2],  i01, dup2(w0.y)); fma2(acc[3],  i23, dup2(w0.y));
        fma2(acc[4],  i01, dup2(w0.z)); fma2(acc[5],  i23, dup2(w0.z));
        fma2(acc[6],  i01, dup2(w0.w)); fma2(acc[7],  i23, dup2(w0.w));
        fma2(acc[8],  i01, dup2(w1.x)); fma2(acc[9],  i23, dup2(w1.x));
        fma2(acc[10], i01, dup2(w1.y)); fma2(acc[11], i23, dup2(w1.y));
        fma2(acc[12], i01, dup2(w1.z)); fma2(acc[13], i23, dup2(w1.z));
        fma2(acc[14], i01, dup2(w1.w)); fma2(acc[15], i23, dup2(w1.w));
    }
}

__device__ __forceinline__ void phaseA(int tid, const float* __restrict__ In,
                                       float* __restrict__ Out) {
    int k = tid >> 5, qc = (tid >> 3) & 3, sq = tid & 7;
    u64 acc[16];
    big_accum<53>(g_wt + OA + k * 32 + qc * 8, In + k * 53 * STR + sq * 4, STR, acc);
    #pragma unroll
    for (int t = 0; t < 8; t++) {
        int q = qc * 8 + t;
        if (q < 27) {
            float2 a = unp(acc[2 * t]), b = unp(acc[2 * t + 1]);
            *(float4*)(Out + (k * 27 + q) * STR + sq * 4) = make_float4(a.x, a.y, b.x, b.y);
        }
    }
}

__device__ __forceinline__ void phaseB(int tid, const float* __restrict__ bias,
                                       const float* __restrict__ In,
                                       float* __restrict__ Out) {
    int l = tid >> 5, s2c = (tid >> 3) & 3, sq = tid & 7;
    u64 acc[16];
    big_accum<27>(g_wt + OB + l * 32 + s2c * 8, In + l * STR + sq * 4, 15 * STR, acc);
    #pragma unroll
    for (int t = 0; t < 8; t++) {
        int s2 = s2c * 8 + t, f = s2 * 15 + l;
        if (s2 < 27 && f < 392) {
            float bb = bias[f];
            float2 a = unp(acc[2 * t]), b = unp(acc[2 * t + 1]);
            *(float4*)(Out + f * STR + sq * 4) = make_float4(
                gelu_f(a.x + bb), gelu_f(a.y + bb), gelu_f(b.x + bb), gelu_f(b.y + bb));
        }
    }
}

// ---------------- medium phases: 240 threads, NOUT outs x 2 samples ----------------
template<int P, int NOUT, int TPAD>
__device__ __forceinline__ void med_mm1(int tid, const float* __restrict__ Wt,
                                        const float* __restrict__ In,
                                        float* __restrict__ Out) {
    if (tid >= 240) return;
    int k = tid >> 4, sp = tid & 15;
    const float* wb = Wt + k * TPAD;
    const float* inb = In + k * P * STR + sp * 2;
    u64 acc[NOUT];
    #pragma unroll
    for (int t = 0; t < NOUT; t++) acc[t] = 0ull;
    #pragma unroll 4
    for (int j = 0; j < P; j++) {
        u64 in2 = *(const u64*)(inb + j * STR);
        #pragma unroll
        for (int t4 = 0; t4 < TPAD; t4 += 4) {
            float4 w = __ldg((const float4*)(wb + j * (15 * TPAD) + t4));
            if (t4 + 0 < NOUT) fma2(acc[t4 + 0], in2, dup2(w.x));
            if (t4 + 1 < NOUT) fma2(acc[t4 + 1], in2, dup2(w.y));
            if (t4 + 2 < NOUT) fma2(acc[t4 + 2], in2, dup2(w.z));
            if (t4 + 3 < NOUT) fma2(acc[t4 + 3], in2, dup2(w.w));
        }
    }
    #pragma unroll
    for (int t = 0; t < NOUT; t++)
        *(float2*)(Out + (k * NOUT + t) * STR + sp * 2) = unp(acc[t]);
}

template<int P, int NOUT, int TPAD>
__device__ __forceinline__ void med_mm2(int tid, const float* __restrict__ Wt,
                                        const float* __restrict__ bias,
                                        const float* __restrict__ In,
                                        float* __restrict__ Out, int nOut) {
    if (tid >= 240) return;
    int l = tid >> 4, sp = tid & 15;
    const float* wb = Wt + l * TPAD;
    const float* inb = In + l * STR + sp * 2;
    u64 acc[NOUT];
    #pragma unroll
    for (int t = 0; t < NOUT; t++) acc[t] = 0ull;
    #pragma unroll 4
    for (int j = 0; j < P; j++) {
        u64 in2 = *(const u64*)(inb + j * 15 * STR);
        #pragma unroll
        for (int t4 = 0; t4 < TPAD; t4 += 4) {
            float4 w = __ldg((const float4*)(wb + j * (15 * TPAD) + t4));
            if (t4 + 0 < NOUT) fma2(acc[t4 + 0], in2, dup2(w.x));
            if (t4 + 1 < NOUT) fma2(acc[t4 + 1], in2, dup2(w.y));
            if (t4 + 2 < NOUT) fma2(acc[t4 + 2], in2, dup2(w.z));
            if (t4 + 3 < NOUT) fma2(acc[t4 + 3], in2, dup2(w.w));
        }
    }
    #pragma unroll
    for (int t = 0; t < NOUT; t++) {
        int f = t * 15 + l;
        if (f < nOut) {
            float bb = bias[f];
            float2 a = unp(acc[t]);
            *(float2*)(Out + f * STR + sp * 2) = make_float2(gelu_f(a.x + bb), gelu_f(a.y + bb));
        }
    }
}

__device__ __forceinline__ void phaseF(int tid, const float* __restrict__ In,
                                       float* __restrict__ Out) {
    if (tid >= 240) return;
    int k = tid >> 4, sp = tid & 15;
    const float* inb = In + k * 5 * STR + sp * 2;
    u64 acc = 0ull;
    #pragma unroll
    for (int j = 0; j < 5; j++) {
        u64 in2 = *(const u64*)(inb + j * STR);
        fma2(acc, in2, dup2(__ldg(g_wt + OF + j * 15 + k)));
    }
    *(float2*)(Out + k * STR + sp * 2) = unp(acc);
}

__device__ __forceinline__ void pad_rows(int tid, float* __restrict__ Out, int lo, int hi) {
    int n = (hi - lo) * TILE;
    for (int i = tid; i < n; i += NT)
        Out[(lo + i / TILE) * STR + (i % TILE)] = 0.f;
}

// ---------------- main fused kernel ----------------
__global__ void __launch_bounds__(NT, 1) monarch_kernel(
    const float* __restrict__ x, int B,
    const float* __restrict__ b1, const float* __restrict__ b2,
    const float* __restrict__ b3, const float* __restrict__ w42,
    const float* __restrict__ b4,
    float* __restrict__ out)
{
    extern __shared__ float sm[];
    float* X = sm;                 // 795 rows x STR
    float* Y = sm + 795 * STR;     // 405 rows x STR
    const int tid = threadIdx.x;
    const int s0 = blockIdx.x * TILE;

    // Load input tile (32 x 784) transposed into X; pad rows 784..794.
    {
        const float* xb = x + (size_t)s0 * 784;
        for (int idx = tid; idx < TILE * 196; idx += NT) {
            int s = idx / 196, i4 = idx - s * 196;
            float4 v = make_float4(0.f, 0.f, 0.f, 0.f);
            if (s0 + s < B) v = __ldcg((const float4*)xb + idx);
            int i = i4 * 4;
            X[(i + 0) * STR + s] = v.x;
            X[(i + 1) * STR + s] = v.y;
            X[(i + 2) * STR + s] = v.z;
            X[(i + 3) * STR + s] = v.w;
        }
        pad_rows(tid, X, 784, 795);
    }
    __syncthreads();

    // Layer 1
    phaseA(tid, X, Y);
    __syncthreads();
    phaseB(tid, b1, Y, X);
    pad_rows(tid, X, 392, 405);
    __syncthreads();

    // Layer 2
    med_mm1<27, 9, 12>(tid, g_wt + OC, X, Y);
    __syncthreads();
    med_mm2<9, 9, 12>(tid, g_wt + OD, b2, Y, X, 128);
    pad_rows(tid, X, 128, 135);
    __syncthreads();

    // Layer 3
    med_mm1<9, 5, 8>(tid, g_wt + OE, X, Y);
    __syncthreads();
    med_mm2<5, 5, 8>(tid, g_wt + OG, b3, Y, X, 64);
    pad_rows(tid, X, 64, 75);
    __syncthreads();

    // Layer 4 mm1
    phaseF(tid, X, Y);
    __syncthreads();

    // Layer 4 mm2 + log-softmax
    if (tid < TILE && s0 + tid < B) {
        const int s = tid;
        float logit[10];
        float m = -1e30f;
        #pragma unroll
        for (int l = 0; l < 10; l++) {
            float v = Y[l * STR + s] * w42[l] + b4[l];
            logit[l] = v;
            m = fmaxf(m, v);
        }
        float sum = 0.f;
        #pragma unroll
        for (int l = 0; l < 10; l++) sum += expf(logit[l] - m);
        float lse = m + logf(sum);
        float* op = out + (size_t)(s0 + s) * 10;
        #pragma unroll
        for (int l = 0; l < 10; l++) op[l] = logit[l] - lse;
    }
}

extern "C" void kernel_launch(void* const* d_in, const int* in_sizes, int n_in,
                              void* d_out, int out_size) {
    const float* x   = (const float*)d_in[0];
    const float* w11 = (const float*)d_in[1];
    const float* w12 = (const float*)d_in[2];
    const float* b1  = (const float*)d_in[3];
    const float* w21 = (const float*)d_in[4];
    const float* w22 = (const float*)d_in[5];
    const float* b2  = (const float*)d_in[6];
    const float* w31 = (const float*)d_in[7];
    const float* w32 = (const float*)d_in[8];
    const float* b3  = (const float*)d_in[9];
    const float* w41 = (const float*)d_in[10];
    const float* w42 = (const float*)d_in[11];
    const float* b4  = (const float*)d_in[12];
    float* out = (float*)d_out;

    int B = in_sizes[0] / 784;

    tw_kernel<<<(WT_TOTAL + 255) / 256, 256>>>(w11, w12, w21, w22, w31, w32, w41);

    int grid = (B + TILE - 1) / TILE;
    size_t smem = SMEM_FLOATS * sizeof(float);
    cudaFuncSetAttribute(monarch_kernel,
                         cudaFuncAttributeMaxDynamicSharedMemorySize, (int)smem);
    monarch_kernel<<<grid, NT, smem>>>(x, B, b1, b2, b3, w42, b4, out);
}

// round 7
// speedup vs baseline: 1.5399x; 1.0234x over previous
#include <cuda_runtime.h>
#include <math.h>

#define TILE 32
#define STR  36          // stride for Y / X (compute buffers), floats
#define SSTR 797         // staging stride (odd -> conflict-free strided LDS)
#define NT   480
#define STAGE_FLOATS (TILE * SSTR)            // 25504
#define SMEM_FLOATS  (STAGE_FLOATS + 405 * STR)  // 25504 + 14580 = 40084 -> 160336 B

typedef unsigned long long u64;

// ---------------- transposed / padded weight scratch ----------------
// A: [j<53][k<15][q<32(pad of 27)]        -> 53*480
// B: [j<27][l<15][s2<32(pad of 27)]       -> 27*480
// C: [j<27][k<15][q<12(pad of 9)]         -> 27*180
// D: [j<9 ][l<15][s2<12(pad of 9)]        -> 9*180
// E: [j<9 ][k<15][q<8 (pad of 5)]         -> 9*120
// G: [j<5 ][l<15][s2<8 (pad of 5)]        -> 5*120
// F: [j<5 ][k<15]                         -> 75
__device__ float g_wt[46635];
#define OA 0
#define OB 25440
#define OC 38400
#define OD 43260
#define OE 44880
#define OG 45960
#define OF 46560
#define WT_TOTAL 46635

__global__ void tw_kernel(const float* __restrict__ w11, const float* __restrict__ w12,
                          const float* __restrict__ w21, const float* __restrict__ w22,
                          const float* __restrict__ w31, const float* __restrict__ w32,
                          const float* __restrict__ w41) {
    int i = blockIdx.x * blockDim.x + threadIdx.x;
    if (i >= WT_TOTAL) return;
    float v;
    if (i < OB) {
        int j = i / 480, r = i % 480, k = r / 32, q = r % 32;
        v = (q < 27) ? w11[(k * 27 + q) * 53 + j] : 0.f;
    } else if (i < OC) {
        int t = i - OB, j = t / 480, r = t % 480, l = r / 32, q = r % 32;
        v = (q < 27) ? w12[(l * 27 + q) * 27 + j] : 0.f;
    } else if (i < OD) {
        int t = i - OC, j = t / 180, r = t % 180, k = r / 12, q = r % 12;
        v = (q < 9) ? w21[(k * 9 + q) * 27 + j] : 0.f;
    } else if (i < OE) {
        int t = i - OD, j = t / 180, r = t % 180, l = r / 12, q = r % 12;
        v = (q < 9) ? w22[(l * 9 + q) * 9 + j] : 0.f;
    } else if (i < OG) {
        int t = i - OE, j = t / 120, r = t % 120, k = r / 8, q = r % 8;
        v = (q < 5) ? w31[(k * 5 + q) * 9 + j] : 0.f;
    } else if (i < OF) {
        int t = i - OG, j = t / 120, r = t % 120, l = r / 8, q = r % 8;
        v = (q < 5) ? w32[(l * 5 + q) * 5 + j] : 0.f;
    } else {
        int t = i - OF, j = t / 15, k = t % 15;
        v = w41[k * 5 + j];
    }
    g_wt[i] = v;
}

// ---------------- packed f32x2 helpers ----------------
__device__ __forceinline__ u64 dup2(float w) {
    u64 r; asm("mov.b64 %0, {%1, %1};" : "=l"(r) : "f"(w)); return r;
}
__device__ __forceinline__ u64 pack2(float a, float b) {
    u64 r; asm("mov.b64 %0, {%1, %2};" : "=l"(r) : "f"(a), "f"(b)); return r;
}
__device__ __forceinline__ void fma2(u64& d, u64 a, u64 b) {
    asm("fma.rn.f32x2 %0, %1, %2, %0;" : "+l"(d) : "l"(a), "l"(b));
}
__device__ __forceinline__ float2 unp(u64 a) {
    float2 f; asm("mov.b64 {%0, %1}, %2;" : "=f"(f.x), "=f"(f.y) : "l"(a)); return f;
}
__device__ __forceinline__ float gelu_f(float v) {
    return 0.5f * v * (1.0f + erff(v * 0.70710678118654752f));
}

// ---------------- phase A: layer-1 mm1 from row-major staging ----------------
// thread = (k, qc, sq): 8 outputs (qc*8..+7 of group k) x 4 samples (sq*4..+3)
__device__ __forceinline__ void phaseA(int tid, const float* __restrict__ S,
                                       float* __restrict__ Out) {
    int k = tid >> 5, qc = (tid >> 3) & 3, sq = tid & 7;
    const float* wb = g_wt + OA + k * 32 + qc * 8;
    const float* inb = S + (sq * 4) * SSTR + k * 53;
    u64 acc[16];
    #pragma unroll
    for (int u = 0; u < 16; u++) acc[u] = 0ull;
    #pragma unroll 4
    for (int j = 0; j < 53; j++) {
        float4 w0 = __ldg((const float4*)(wb + j * 480));
        float4 w1 = __ldg((const float4*)(wb + j * 480 + 4));
        float x0 = inb[j];
        float x1 = inb[SSTR + j];
        float x2 = inb[2 * SSTR + j];
        float x3 = inb[3 * SSTR + j];
        u64 i01 = pack2(x0, x1), i23 = pack2(x2, x3);
        fma2(acc[0],  i01, dup2(w0.x)); fma2(acc[1],  i23, dup2(w0.x));
        fma2(acc[2],  i01, dup2(w0.y)); fma2(acc[3],  i23, dup2(w0.y));
        fma2(acc[4],  i01, dup2(w0.z)); fma2(acc[5],  i23, dup2(w0.z));
        fma2(acc[6],  i01, dup2(w0.w)); fma2(acc[7],  i23, dup2(w0.w));
        fma2(acc[8],  i01, dup2(w1.x)); fma2(acc[9],  i23, dup2(w1.x));
        fma2(acc[10], i01, dup2(w1.y)); fma2(acc[11], i23, dup2(w1.y));
        fma2(acc[12], i01, dup2(w1.z)); fma2(acc[13], i23, dup2(w1.z));
        fma2(acc[14], i01, dup2(w1.w)); fma2(acc[15], i23, dup2(w1.w));
    }
    #pragma unroll
    for (int t = 0; t < 8; t++) {
        int q = qc * 8 + t;
        if (q < 27) {
            float2 a = unp(acc[2 * t]), b = unp(acc[2 * t + 1]);
            *(float4*)(Out + (k * 27 + q) * STR + sq * 4) = make_float4(a.x, a.y, b.x, b.y);
        }
    }
}

// ---------------- phase B: layer-1 permute+mm2+gelu (Y -> X) ----------------
__device__ __forceinline__ void phaseB(int tid, const float* __restrict__ bias,
                                       const float* __restrict__ In,
                                       float* __restrict__ Out) {
    int l = tid >> 5, s2c = (tid >> 3) & 3, sq = tid & 7;
    const float* wb = g_wt + OB + l * 32 + s2c * 8;
    const float* inb = In + l * STR + sq * 4;
    u64 acc[16];
    #pragma unroll
    for (int u = 0; u < 16; u++) acc[u] = 0ull;
    #pragma unroll 4
    for (int j = 0; j < 27; j++) {
        float4 w0 = __ldg((const float4*)(wb + j * 480));
        float4 w1 = __ldg((const float4*)(wb + j * 480 + 4));
        const float* ip = inb + j * 15 * STR;
        u64 i01 = *(const u64*)(ip);
        u64 i23 = *(const u64*)(ip + 2);
        fma2(acc[0],  i01, dup2(w0.x)); fma2(acc[1],  i23, dup2(w0.x));
        fma2(acc[2],  i01, dup2(w0.y)); fma2(acc[3],  i23, dup2(w0.y));
        fma2(acc[4],  i01, dup2(w0.z)); fma2(acc[5],  i23, dup2(w0.z));
        fma2(acc[6],  i01, dup2(w0.w)); fma2(acc[7],  i23, dup2(w0.w));
        fma2(acc[8],  i01, dup2(w1.x)); fma2(acc[9],  i23, dup2(w1.x));
        fma2(acc[10], i01, dup2(w1.y)); fma2(acc[11], i23, dup2(w1.y));
        fma2(acc[12], i01, dup2(w1.z)); fma2(acc[13], i23, dup2(w1.z));
        fma2(acc[14], i01, dup2(w1.w)); fma2(acc[15], i23, dup2(w1.w));
    }
    #pragma unroll
    for (int t = 0; t < 8; t++) {
        int s2 = s2c * 8 + t, f = s2 * 15 + l;
        if (s2 < 27 && f < 392) {
            float bb = bias[f];
            float2 a = unp(acc[2 * t]), b = unp(acc[2 * t + 1]);
            *(float4*)(Out + f * STR + sq * 4) = make_float4(
                gelu_f(a.x + bb), gelu_f(a.y + bb), gelu_f(b.x + bb), gelu_f(b.y + bb));
        }
    }
}

// ---------------- medium phases: 240 threads, NOUT outs x 2 samples ----------------
template<int P, int NOUT, int TPAD>
__device__ __forceinline__ void med_mm1(int tid, const float* __restrict__ Wt,
                                        const float* __restrict__ In,
                                        float* __restrict__ Out) {
    if (tid >= 240) return;
    int k = tid >> 4, sp = tid & 15;
    const float* wb = Wt + k * TPAD;
    const float* inb = In + k * P * STR + sp * 2;
    u64 acc[NOUT];
    #pragma unroll
    for (int t = 0; t < NOUT; t++) acc[t] = 0ull;
    #pragma unroll 4
    for (int j = 0; j < P; j++) {
        u64 in2 = *(const u64*)(inb + j * STR);
        #pragma unroll
        for (int t4 = 0; t4 < TPAD; t4 += 4) {
            float4 w = __ldg((const float4*)(wb + j * (15 * TPAD) + t4));
            if (t4 + 0 < NOUT) fma2(acc[t4 + 0], in2, dup2(w.x));
            if (t4 + 1 < NOUT) fma2(acc[t4 + 1], in2, dup2(w.y));
            if (t4 + 2 < NOUT) fma2(acc[t4 + 2], in2, dup2(w.z));
            if (t4 + 3 < NOUT) fma2(acc[t4 + 3], in2, dup2(w.w));
        }
    }
    #pragma unroll
    for (int t = 0; t < NOUT; t++)
        *(float2*)(Out + (k * NOUT + t) * STR + sp * 2) = unp(acc[t]);
}

template<int P, int NOUT, int TPAD>
__device__ __forceinline__ void med_mm2(int tid, const float* __restrict__ Wt,
                                        const float* __restrict__ bias,
                                        const float* __restrict__ In,
                                        float* __restrict__ Out, int nOut) {
    if (tid >= 240) return;
    int l = tid >> 4, sp = tid & 15;
    const float* wb = Wt + l * TPAD;
    const float* inb = In + l * STR + sp * 2;
    u64 acc[NOUT];
    #pragma unroll
    for (int t = 0; t < NOUT; t++) acc[t] = 0ull;
    #pragma unroll 4
    for (int j = 0; j < P; j++) {
        u64 in2 = *(const u64*)(inb + j * 15 * STR);
        #pragma unroll
        for (int t4 = 0; t4 < TPAD; t4 += 4) {
            float4 w = __ldg((const float4*)(wb + j * (15 * TPAD) + t4));
            if (t4 + 0 < NOUT) fma2(acc[t4 + 0], in2, dup2(w.x));
            if (t4 + 1 < NOUT) fma2(acc[t4 + 1], in2, dup2(w.y));
            if (t4 + 2 < NOUT) fma2(acc[t4 + 2], in2, dup2(w.z));
            if (t4 + 3 < NOUT) fma2(acc[t4 + 3], in2, dup2(w.w));
        }
    }
    #pragma unroll
    for (int t = 0; t < NOUT; t++) {
        int f = t * 15 + l;
        if (f < nOut) {
            float bb = bias[f];
            float2 a = unp(acc[t]);
            *(float2*)(Out + f * STR + sp * 2) = make_float2(gelu_f(a.x + bb), gelu_f(a.y + bb));
        }
    }
}

__device__ __forceinline__ void phaseF(int tid, const float* __restrict__ In,
                                       float* __restrict__ Out) {
    if (tid >= 240) return;
    int k = tid >> 4, sp = tid & 15;
    const float* inb = In + k * 5 * STR + sp * 2;
    u64 acc = 0ull;
    #pragma unroll
    for (int j = 0; j < 5; j++) {
        u64 in2 = *(const u64*)(inb + j * STR);
        fma2(acc, in2, dup2(__ldg(g_wt + OF + j * 15 + k)));
    }
    *(float2*)(Out + k * STR + sp * 2) = unp(acc);
}

__device__ __forceinline__ void pad_rows(int tid, float* __restrict__ Out, int lo, int hi) {
    int n = (hi - lo) * TILE;
    for (int i = tid; i < n; i += NT)
        Out[(lo + i / TILE) * STR + (i % TILE)] = 0.f;
}

// ---------------- main fused kernel ----------------
__global__ void __launch_bounds__(NT, 1) monarch_kernel(
    const float* __restrict__ x, int B,
    const float* __restrict__ b1, const float* __restrict__ b2,
    const float* __restrict__ b3, const float* __restrict__ w42,
    const float* __restrict__ b4,
    float* __restrict__ out)
{
    extern __shared__ float sm[];
    float* S = sm;                      // staging: 32 x SSTR (row-major input)
    float* X = sm;                      // layers 2+ activations (aliases staging)
    float* Y = sm + STAGE_FLOATS;       // 405 rows x STR
    const int tid = threadIdx.x;
    const int s0 = blockIdx.x * TILE;

    // Load input tile (32 x 784) ROW-MAJOR into staging (coalesced LDG.128,
    // conflict-free scalar STS). Zero-pad features 784..794.
    {
        const float* xb = x + (size_t)s0 * 784;
        for (int idx = tid; idx < TILE * 196; idx += NT) {
            int s = idx / 196, c4 = idx - s * 196;
            float4 v = make_float4(0.f, 0.f, 0.f, 0.f);
            if (s0 + s < B) v = __ldcg((const float4*)xb + idx);
            float* d = S + s * SSTR + c4 * 4;
            d[0] = v.x; d[1] = v.y; d[2] = v.z; d[3] = v.w;
        }
        for (int i = tid; i < TILE * 11; i += NT)
            S[(i / 11) * SSTR + 784 + (i % 11)] = 0.f;
    }
    __syncthreads();

    // Layer 1
    phaseA(tid, S, Y);
    __syncthreads();
    phaseB(tid, b1, Y, X);      // X overwrites staging (staging dead after phaseA)
    pad_rows(tid, X, 392, 405);
    __syncthreads();

    // Layer 2
    med_mm1<27, 9, 12>(tid, g_wt + OC, X, Y);
    __syncthreads();
    med_mm2<9, 9, 12>(tid, g_wt + OD, b2, Y, X, 128);
    pad_rows(tid, X, 128, 135);
    __syncthreads();

    // Layer 3
    med_mm1<9, 5, 8>(tid, g_wt + OE, X, Y);
    __syncthreads();
    med_mm2<5, 5, 8>(tid, g_wt + OG, b3, Y, X, 64);
    pad_rows(tid, X, 64, 75);
    __syncthreads();

    // Layer 4 mm1
    phaseF(tid, X, Y);
    __syncthreads();

    // Layer 4 mm2 + log-softmax
    if (tid < TILE && s0 + tid < B) {
        const int s = tid;
        float logit[10];
        float m = -1e30f;
        #pragma unroll
        for (int l = 0; l < 10; l++) {
            float v = Y[l * STR + s] * w42[l] + b4[l];
            logit[l] = v;
            m = fmaxf(m, v);
        }
        float sum = 0.f;
        #pragma unroll
        for (int l = 0; l < 10; l++) sum += expf(logit[l] - m);
        float lse = m + logf(sum);
        float* op = out + (size_t)(s0 + s) * 10;
        #pragma unroll
        for (int l = 0; l < 10; l++) op[l] = logit[l] - lse;
    }
}

extern "C" void kernel_launch(void* const* d_in, const int* in_sizes, int n_in,
                              void* d_out, int out_size) {
    const float* x   = (const float*)d_in[0];
    const float* w11 = (const float*)d_in[1];
    const float* w12 = (const float*)d_in[2];
    const float* b1  = (const float*)d_in[3];
    const float* w21 = (const float*)d_in[4];
    const float* w22 = (const float*)d_in[5];
    const float* b2  = (const float*)d_in[6];
    const float* w31 = (const float*)d_in[7];
    const float* w32 = (const float*)d_in[8];
    const float* b3  = (const float*)d_in[9];
    const float* w41 = (const float*)d_in[10];
    const float* w42 = (const float*)d_in[11];
    const float* b4  = (const float*)d_in[12];
    float* out = (float*)d_out;

    int B = in_sizes[0] / 784;

    tw_kernel<<<(WT_TOTAL + 255) / 256, 256>>>(w11, w12, w21, w22, w31, w32, w41);

    int grid = (B + TILE - 1) / TILE;
    size_t smem = SMEM_FLOATS * sizeof(float);
    cudaFuncSetAttribute(monarch_kernel,
                         cudaFuncAttributeMaxDynamicSharedMemorySize, (int)smem);
    monarch_kernel<<<grid, NT, smem>>>(x, B, b1, b2, b3, w42, b4, out);
}